// round 9
// baseline (speedup 1.0000x reference)
#include <cuda_runtime.h>
#include <cuda_bf16.h>
#include <cstdint>

// Problem constants: T=2048, N=64, D=1024
#define T_DIM 2048
#define N_DIM 64
#define D_DIM 1024
#define D_VEC 256                 // float4 per row
#define VEC_PER_LANE 8            // 256 / 32 lanes
#define TILE_T 4                  // rows per tile (= warps per block)
#define NBX 32                    // blocks per sequence (strided tile ownership)
#define NSTAGES 3
#define NWARPS 4
#define NTHREADS 128
#define CHUNKS_PER_THREAD ((TILE_T * D_VEC) / NTHREADS)   // 8 x 16B per thread
#define HALF_LOG_2PI 0.91893853320467274178f
#define EPS_VAR 1e-6f

__global__ void zero_out_kernel(float* __restrict__ out) {
    if (threadIdx.x < N_DIM) out[threadIdx.x] = 0.0f;
}

__device__ __forceinline__ void cp_async16(unsigned int saddr, const void* gptr) {
    asm volatile("cp.async.cg.shared.global [%0], [%1], 16;\n"
                 :: "r"(saddr), "l"(gptr));
}
__device__ __forceinline__ void cp_commit() {
    asm volatile("cp.async.commit_group;\n" ::: "memory");
}
__device__ __forceinline__ void cp_wait2() {
    asm volatile("cp.async.wait_group 2;\n" ::: "memory");
}

__global__ __launch_bounds__(NTHREADS, 4)
void gnll_kernel(const float* __restrict__ y,     // (T, N)
                 const float4* __restrict__ x4,   // (T, N, D/4)
                 const float4* __restrict__ W4,   // (2, D/4)
                 const int* __restrict__ lens,    // (N,)
                 float* __restrict__ out)         // (N,)
{
    __shared__ float4 buf[NSTAGES][TILE_T * D_VEC];   // 3 x 16KB
    __shared__ float  s_partial[NWARPS];

    const int n    = blockIdx.y;
    const int bx   = blockIdx.x;
    const int len  = lens[n];
    const int tid  = threadIdx.x;
    const int wid  = tid >> 5;
    const int lane = tid & 31;

    // Tiles owned by this block: j = bx + k*NBX, rows [j*TILE_T, (j+1)*TILE_T)
    int kmax = 0;
    {
        int jlim = (len + TILE_T - 1) / TILE_T;   // tiles containing any valid row
        if (bx < jlim) kmax = (jlim - bx + NBX - 1) / NBX;
    }
    if (kmax == 0) return;

    // Preload W lane-striped into registers (64 regs; launch_bounds grants 128).
    float4 w0[VEC_PER_LANE], w1[VEC_PER_LANE];
    #pragma unroll
    for (int i = 0; i < VEC_PER_LANE; i++) {
        w0[i] = W4[i * 32 + lane];
        w1[i] = W4[D_VEC + i * 32 + lane];
    }

    // Issue one tile's cp.asyncs (skipping rows >= len) and commit a group.
    // All threads execute this uniformly: exactly one commit_group per call.
    auto issue_tile = [&](int k, int stage) {
        const int t0 = (bx + k * NBX) * TILE_T;
        unsigned int sbase = (unsigned int)__cvta_generic_to_shared(&buf[stage][0]);
        #pragma unroll
        for (int c = 0; c < CHUNKS_PER_THREAD; c++) {
            int idx = tid + c * NTHREADS;          // 0..1023 float4 slots
            int t   = t0 + (idx >> 8);             // row within tile
            if (t < len) {
                const float4* g = x4 + ((size_t)t * N_DIM + n) * D_VEC + (idx & 255);
                cp_async16(sbase + (unsigned int)idx * 16u, g);
            }
        }
        cp_commit();
    };

    // Prologue: always commit exactly NSTAGES groups.
    #pragma unroll
    for (int s = 0; s < NSTAGES; s++) {
        if (s < kmax) issue_tile(s, s); else cp_commit();
    }

    float warp_sum = 0.0f;
    int stage = 0;

    for (int k = 0; k < kmax; k++) {
        // Invariant: groups for tiles k, k+1, k+2 are the pending ones.
        cp_wait2();        // tile k's group has completed
        __syncthreads();

        const int t = (bx + k * NBX) * TILE_T + wid;   // this warp's row
        if (t < len) {
            const float4* src = &buf[stage][wid * D_VEC];
            float a0 = 0.0f, a1 = 0.0f;
            #pragma unroll
            for (int i = 0; i < VEC_PER_LANE; i++) {
                float4 v = src[i * 32 + lane];
                a0 = fmaf(v.x, w0[i].x, a0);
                a0 = fmaf(v.y, w0[i].y, a0);
                a0 = fmaf(v.z, w0[i].z, a0);
                a0 = fmaf(v.w, w0[i].w, a0);
                a1 = fmaf(v.x, w1[i].x, a1);
                a1 = fmaf(v.y, w1[i].y, a1);
                a1 = fmaf(v.z, w1[i].z, a1);
                a1 = fmaf(v.w, w1[i].w, a1);
            }
            #pragma unroll
            for (int off = 16; off > 0; off >>= 1) {
                a0 += __shfl_xor_sync(0xFFFFFFFFu, a0, off);
                a1 += __shfl_xor_sync(0xFFFFFFFFu, a1, off);
            }
            if (lane == 0) {
                float mu  = a0;
                float var = fmaxf(1.0f / (1.0f + __expf(-a1)), EPS_VAR);
                float d   = y[t * N_DIM + n] - mu;
                warp_sum += 0.5f * (__logf(var) + d * d / var) + HALF_LOG_2PI;
            }
        }
        __syncthreads();   // all warps done reading this stage

        // Refill the just-consumed stage; exactly one commit per iteration.
        if (k + NSTAGES < kmax) issue_tile(k + NSTAGES, stage); else cp_commit();

        stage = (stage + 1 == NSTAGES) ? 0 : stage + 1;
    }

    if (lane == 0) s_partial[wid] = warp_sum;
    __syncthreads();
    if (tid == 0) {
        float s = s_partial[0] + s_partial[1] + s_partial[2] + s_partial[3];
        atomicAdd(&out[n], s);
    }
}

extern "C" void kernel_launch(void* const* d_in, const int* in_sizes, int n_in,
                              void* d_out, int out_size) {
    // metadata order: y (T*N f32), x (T*N*D f32), W (2*D f32), lens (N i32)
    const float*  y    = (const float*)d_in[0];
    const float4* x4   = (const float4*)d_in[1];
    const float4* W4   = (const float4*)d_in[2];
    const int*    lens = (const int*)d_in[3];
    float*        out  = (float*)d_out;

    zero_out_kernel<<<1, 64>>>(out);

    dim3 grid(NBX, N_DIM);
    dim3 block(NTHREADS);
    gnll_kernel<<<grid, block>>>(y, x4, W4, lens, out);
}

// round 10
// speedup vs baseline: 1.0287x; 1.0287x over previous
#include <cuda_runtime.h>
#include <cuda_bf16.h>
#include <cstdint>

// Problem constants: T=2048, N=64, D=1024
#define T_DIM 2048
#define N_DIM 64
#define D_VEC 256                 // float4 per row
#define VEC_PER_LANE 8            // 256 / 32 lanes
#define NWARPS 4
#define NTHREADS 128
#define NBX 32                    // 32 blocks * 4 warps = 128 streams per sequence
#define NSTREAMS 128              // rows t = s + 128*k belong to stream s
#define NSTAGES 2
#define HALF_LOG_2PI 0.91893853320467274178f
#define EPS_VAR 1e-6f

__global__ void zero_out_kernel(float* __restrict__ out) {
    if (threadIdx.x < N_DIM) out[threadIdx.x] = 0.0f;
}

__device__ __forceinline__ void cp_async16(unsigned int saddr, const void* gptr) {
    asm volatile("cp.async.cg.shared.global [%0], [%1], 16;\n"
                 :: "r"(saddr), "l"(gptr));
}
__device__ __forceinline__ void cp_commit() {
    asm volatile("cp.async.commit_group;\n" ::: "memory");
}
__device__ __forceinline__ void cp_wait1() {
    asm volatile("cp.async.wait_group 1;\n" ::: "memory");
}

__global__ __launch_bounds__(NTHREADS, 4)
void gnll_kernel(const float* __restrict__ y,     // (T, N)
                 const float4* __restrict__ x4,   // (T, N, D/4)
                 const float4* __restrict__ W4,   // (2, D/4)
                 const int* __restrict__ lens,    // (N,)
                 float* __restrict__ out)         // (N,)
{
    // Per-warp private double buffer: 2 stages x 4KB per warp. No block sync.
    __shared__ float4 buf[NWARPS][NSTAGES][D_VEC];

    const int n    = blockIdx.y;
    const int bx   = blockIdx.x;
    const int len  = lens[n];
    const int tid  = threadIdx.x;
    const int wid  = tid >> 5;
    const int lane = tid & 31;

    // Warp-private stream: rows t = s + 128*k, all strictly < len by kmax.
    const int s = bx * NWARPS + wid;               // 0..127, warp-uniform
    const int kmax = (len > s) ? ((len - s + NSTREAMS - 1) >> 7) : 0;
    if (kmax == 0) return;                         // warp-uniform exit

    // Preload W lane-striped into registers (64 regs).
    float4 w0[VEC_PER_LANE], w1[VEC_PER_LANE];
    #pragma unroll
    for (int i = 0; i < VEC_PER_LANE; i++) {
        w0[i] = W4[i * 32 + lane];
        w1[i] = W4[D_VEC + i * 32 + lane];
    }

    // Issue one full row (4KB) into this warp's stage st; one commit per call.
    // Lane l writes slots {c*32+l}; it later reads exactly those slots, so
    // per-thread wait_group suffices — no __syncwarp needed.
    auto issue = [&](int k, int st) {
        const int t = s + (k << 7);
        const float4* g = x4 + ((size_t)t * N_DIM + n) * D_VEC + lane;
        unsigned int sb = (unsigned int)__cvta_generic_to_shared(&buf[wid][st][lane]);
        #pragma unroll
        for (int c = 0; c < VEC_PER_LANE; c++)
            cp_async16(sb + (unsigned int)c * 32u * 16u, g + c * 32);
        cp_commit();
    };

    // Prologue: always exactly NSTAGES commits.
    issue(0, 0);
    if (kmax > 1) issue(1, 1); else cp_commit();

    float warp_sum = 0.0f;

    for (int k = 0; k < kmax; k++) {
        cp_wait1();                          // tile k's group complete
        const int st = k & 1;
        const float4* src = &buf[wid][st][0];

        float a0 = 0.0f, a1 = 0.0f;
        #pragma unroll
        for (int i = 0; i < VEC_PER_LANE; i++) {
            float4 v = src[i * 32 + lane];
            a0 = fmaf(v.x, w0[i].x, a0);
            a0 = fmaf(v.y, w0[i].y, a0);
            a0 = fmaf(v.z, w0[i].z, a0);
            a0 = fmaf(v.w, w0[i].w, a0);
            a1 = fmaf(v.x, w1[i].x, a1);
            a1 = fmaf(v.y, w1[i].y, a1);
            a1 = fmaf(v.z, w1[i].z, a1);
            a1 = fmaf(v.w, w1[i].w, a1);
        }

        // Refill the consumed stage immediately (before the reduce chain) so
        // the next tile's DRAM fetch overlaps the shuffle latency.
        if (k + NSTAGES < kmax) issue(k + NSTAGES, st); else cp_commit();

        #pragma unroll
        for (int off = 16; off > 0; off >>= 1) {
            a0 += __shfl_xor_sync(0xFFFFFFFFu, a0, off);
            a1 += __shfl_xor_sync(0xFFFFFFFFu, a1, off);
        }
        if (lane == 0) {
            const int t = s + (k << 7);
            float mu  = a0;
            float var = fmaxf(1.0f / (1.0f + __expf(-a1)), EPS_VAR);
            float d   = y[t * N_DIM + n] - mu;
            warp_sum += 0.5f * (__logf(var) + d * d / var) + HALF_LOG_2PI;
        }
    }

    if (lane == 0) atomicAdd(&out[n], warp_sum);
}

extern "C" void kernel_launch(void* const* d_in, const int* in_sizes, int n_in,
                              void* d_out, int out_size) {
    // metadata order: y (T*N f32), x (T*N*D f32), W (2*D f32), lens (N i32)
    const float*  y    = (const float*)d_in[0];
    const float4* x4   = (const float4*)d_in[1];
    const float4* W4   = (const float4*)d_in[2];
    const int*    lens = (const int*)d_in[3];
    float*        out  = (float*)d_out;

    zero_out_kernel<<<1, 64>>>(out);

    dim3 grid(NBX, N_DIM);
    dim3 block(NTHREADS);
    gnll_kernel<<<grid, block>>>(y, x4, W4, lens, out);
}

// round 11
// speedup vs baseline: 1.0343x; 1.0054x over previous
#include <cuda_runtime.h>
#include <cuda_bf16.h>
#include <cstdint>

// Problem constants: T=2048, N=64, D=1024
#define T_DIM 2048
#define N_DIM 64
#define D_VEC 256                 // float4 per row
#define VEC_PER_LANE 8            // 256 / 32 lanes
#define NWARPS 4
#define NTHREADS 128
#define NBX 32                    // 32 blocks * 4 warps = 128 streams per sequence
#define NSTREAMS 128              // rows t = s + 128*k belong to stream s
#define NSTAGES 2
#define HALF_LOG_2PI 0.91893853320467274178f
#define EPS_VAR 1e-6f

__global__ void zero_out_kernel(float* __restrict__ out) {
    if (threadIdx.x < N_DIM) out[threadIdx.x] = 0.0f;
}

__device__ __forceinline__ void cp_async16(unsigned int saddr, const void* gptr) {
    asm volatile("cp.async.cg.shared.global [%0], [%1], 16;\n"
                 :: "r"(saddr), "l"(gptr));
}
__device__ __forceinline__ void cp_commit() {
    asm volatile("cp.async.commit_group;\n" ::: "memory");
}
__device__ __forceinline__ void cp_wait1() {
    asm volatile("cp.async.wait_group 1;\n" ::: "memory");
}

// 5 blocks/SM: reg target 65536/(5*128)=102 >= the 99 this kernel needs,
// smem 5 x 33KB = 165KB < 228KB. Raises streams/SM 16 -> 20.
__global__ __launch_bounds__(NTHREADS, 5)
void gnll_kernel(const float* __restrict__ y,     // (T, N)
                 const float4* __restrict__ x4,   // (T, N, D/4)
                 const float4* __restrict__ W4,   // (2, D/4)
                 const int* __restrict__ lens,    // (N,)
                 float* __restrict__ out)         // (N,)
{
    // Per-warp private double buffer: 2 stages x 4KB per warp. No block sync.
    __shared__ float4 buf[NWARPS][NSTAGES][D_VEC];

    const int n    = blockIdx.y;
    const int bx   = blockIdx.x;
    const int len  = lens[n];
    const int tid  = threadIdx.x;
    const int wid  = tid >> 5;
    const int lane = tid & 31;

    // Warp-private stream: rows t = s + 128*k, all strictly < len by kmax.
    const int s = bx * NWARPS + wid;               // 0..127, warp-uniform
    const int kmax = (len > s) ? ((len - s + NSTREAMS - 1) >> 7) : 0;
    if (kmax == 0) return;                         // warp-uniform exit

    // Preload W lane-striped into registers (64 regs).
    float4 w0[VEC_PER_LANE], w1[VEC_PER_LANE];
    #pragma unroll
    for (int i = 0; i < VEC_PER_LANE; i++) {
        w0[i] = W4[i * 32 + lane];
        w1[i] = W4[D_VEC + i * 32 + lane];
    }

    // Issue one full row (4KB) into this warp's stage st; one commit per call.
    // Lane l writes slots {c*32+l}; it later reads exactly those slots, so
    // per-thread wait_group suffices — no __syncwarp needed.
    auto issue = [&](int k, int st) {
        const int t = s + (k << 7);
        const float4* g = x4 + ((size_t)t * N_DIM + n) * D_VEC + lane;
        unsigned int sb = (unsigned int)__cvta_generic_to_shared(&buf[wid][st][lane]);
        #pragma unroll
        for (int c = 0; c < VEC_PER_LANE; c++)
            cp_async16(sb + (unsigned int)c * 32u * 16u, g + c * 32);
        cp_commit();
    };

    // Prologue: always exactly NSTAGES commits.
    issue(0, 0);
    if (kmax > 1) issue(1, 1); else cp_commit();

    float warp_sum = 0.0f;

    for (int k = 0; k < kmax; k++) {
        cp_wait1();                          // tile k's group complete
        const int st = k & 1;
        const float4* src = &buf[wid][st][0];

        float a0 = 0.0f, a1 = 0.0f;
        #pragma unroll
        for (int i = 0; i < VEC_PER_LANE; i++) {
            float4 v = src[i * 32 + lane];
            a0 = fmaf(v.x, w0[i].x, a0);
            a0 = fmaf(v.y, w0[i].y, a0);
            a0 = fmaf(v.z, w0[i].z, a0);
            a0 = fmaf(v.w, w0[i].w, a0);
            a1 = fmaf(v.x, w1[i].x, a1);
            a1 = fmaf(v.y, w1[i].y, a1);
            a1 = fmaf(v.z, w1[i].z, a1);
            a1 = fmaf(v.w, w1[i].w, a1);
        }

        // Refill the consumed stage immediately (before the reduce chain) so
        // the next tile's DRAM fetch overlaps the shuffle latency.
        if (k + NSTAGES < kmax) issue(k + NSTAGES, st); else cp_commit();

        #pragma unroll
        for (int off = 16; off > 0; off >>= 1) {
            a0 += __shfl_xor_sync(0xFFFFFFFFu, a0, off);
            a1 += __shfl_xor_sync(0xFFFFFFFFu, a1, off);
        }
        if (lane == 0) {
            const int t = s + (k << 7);
            float mu  = a0;
            float var = fmaxf(1.0f / (1.0f + __expf(-a1)), EPS_VAR);
            float d   = y[t * N_DIM + n] - mu;
            warp_sum += 0.5f * (__logf(var) + d * d / var) + HALF_LOG_2PI;
        }
    }

    if (lane == 0) atomicAdd(&out[n], warp_sum);
}

extern "C" void kernel_launch(void* const* d_in, const int* in_sizes, int n_in,
                              void* d_out, int out_size) {
    // metadata order: y (T*N f32), x (T*N*D f32), W (2*D f32), lens (N i32)
    const float*  y    = (const float*)d_in[0];
    const float4* x4   = (const float4*)d_in[1];
    const float4* W4   = (const float4*)d_in[2];
    const int*    lens = (const int*)d_in[3];
    float*        out  = (float*)d_out;

    zero_out_kernel<<<1, 64>>>(out);

    dim3 grid(NBX, N_DIM);
    dim3 block(NTHREADS);
    gnll_kernel<<<grid, block>>>(y, x4, W4, lens, out);
}